// round 9
// baseline (speedup 1.0000x reference)
#include <cuda_runtime.h>
#include <cstdint>

#define CCH 12
#define LL 8192
#define NB 512
#define PT 512                    // output positions per block
#define HALO 160
#define WROWS (PT + 2*HALO)       // 832 window rows
#define ROWF 20                   // padded row width in floats (80B -> conflict-free A loads)
#define NTILES (LL/PT)            // 16
#define NF 90
#define NTH 256
#define NEGINF __int_as_float(0xff800000)

// Per-(n, filter, tile) partials: x = count(conv+b > 0), y = max(conv+b)
__device__ float2 g_part[NB * NF * NTILES];

__device__ __forceinline__ uint32_t f2tf32(float x){
    uint32_t r; asm("cvt.rna.tf32.f32 %0, %1;" : "=r"(r) : "f"(x)); return r;
}

// m16n8k8 tf32 MMA, D += A*B (fp32 accumulate)
__device__ __forceinline__ void mma8(float* c, const uint32_t* a, const uint32_t* b){
    asm volatile("mma.sync.aligned.m16n8k8.row.col.f32.tf32.tf32.f32 "
        "{%0,%1,%2,%3}, {%4,%5,%6,%7}, {%8,%9}, {%0,%1,%2,%3};"
        : "+f"(c[0]), "+f"(c[1]), "+f"(c[2]), "+f"(c[3])
        : "r"(a[0]), "r"(a[1]), "r"(a[2]), "r"(a[3]), "r"(b[0]), "r"(b[1]));
}

// smem layout (uint32 units):
//   pHi[WROWS*ROWF], pLo[WROWS*ROWF]    x tile, tf32 hi/lo split, position-major 16ch rows
//   bbuf[88*64]                          B fragments: combo=((m*2+kc)*2+split)*2+nf, 32 lanes x 2 regs
//   bias[16], red[8*16*2]
__global__ void __launch_bounds__(NTH, 1) rocket_mma_kernel(
    const float* __restrict__ x,
    const float* __restrict__ W7,  const float* __restrict__ b7,
    const float* __restrict__ W9,  const float* __restrict__ b9,
    const float* __restrict__ W11, const float* __restrict__ b11)
{
    extern __shared__ uint32_t sm[];
    uint32_t* pHi   = sm;
    uint32_t* pLo   = sm + WROWS*ROWF;
    uint32_t* bbuf  = pLo + WROWS*ROWF;          // 88*64 = 5632
    float*    bias_s = (float*)(bbuf + 88*64);    // 16
    float*    red    = bias_s + 16;               // 8*16*2 = 256

    const int t    = threadIdx.x;
    const int lane = t & 31, w = t >> 5;
    const int lq   = lane >> 2, tq = lane & 3;
    const int tile = blockIdx.x, n = blockIdx.y;
    const int tile0 = tile * PT;

    // ---- Fill x tile: transpose to position-major, split into tf32 hi/lo planes ----
    const float* xn = x + (size_t)n * CCH * LL;
    for (int c = 0; c < CCH; c++){
        const float* xc = xn + (size_t)c * LL;
        for (int i = t; i < WROWS; i += NTH){
            int gp = tile0 - HALO + i;
            float v = (gp >= 0 && gp < LL) ? xc[gp] : 0.0f;
            uint32_t hi = f2tf32(v);
            pHi[i*ROWF + c] = hi;
            pLo[i*ROWF + c] = f2tf32(v - __uint_as_float(hi));
        }
    }
    for (int i = t; i < WROWS; i += NTH){
        #pragma unroll
        for (int c = CCH; c < 16; c++){ pHi[i*ROWF+c] = 0u; pLo[i*ROWF+c] = 0u; }
    }

    for (int dlog = 0; dlog < 6; dlog++){
        const int d = 1 << dlog;
        __syncthreads();   // tile/red/bbuf reuse fence

        // ---- Build B fragments (hi/lo tf32) + bias for this dilation ----
        for (int idx = t; idx < 88*32; idx += NTH){
            int l2 = idx & 31, combo = idx >> 5;
            int nf = combo & 1, split = (combo>>1)&1, kc = (combo>>2)&1, m = combo>>3;
            int tap = m - 5;
            int colg = l2 >> 2, kq = l2 & 3;
            int filt = nf*8 + colg;
            #pragma unroll
            for (int reg = 0; reg < 2; reg++){
                int ch = kc*8 + kq + reg*4;
                float wv = 0.0f;
                if (filt < 15 && ch < CCH){
                    int g = filt / 5, f = filt - g*5;
                    int hk = 3 + g;
                    if (tap >= -hk && tap <= hk){
                        int K = 7 + 2*g;
                        const float* Wg = (g==0) ? W7 : (g==1) ? W9 : W11;
                        wv = Wg[((size_t)(dlog*5 + f)*CCH + ch)*K + (tap + hk)];
                    }
                }
                uint32_t hi = f2tf32(wv);
                bbuf[combo*64 + l2*2 + reg] =
                    split ? f2tf32(wv - __uint_as_float(hi)) : hi;
            }
        }
        if (t < 16){
            float bv = 0.0f;
            if (t < 15){
                int g = t/5, f = t - g*5;
                const float* bg = (g==0) ? b7 : (g==1) ? b9 : b11;
                bv = bg[dlog*5 + f];
            }
            bias_s[t] = bv;
        }
        __syncthreads();

        // ---- Mainloop: 11 shifted GEMM taps, 3xTF32 accumulation ----
        float acc[4][2][4];
        #pragma unroll
        for (int i = 0; i < 4; i++)
            #pragma unroll
            for (int nf = 0; nf < 2; nf++)
                #pragma unroll
                for (int j = 0; j < 4; j++) acc[i][nf][j] = 0.0f;

        const int rbase = w*64 + HALO + lq;

        #pragma unroll
        for (int m = 0; m < 11; m++){
            const int ro = (m - 5) * d;
            const bool nf0live = (m >= 1 && m <= 9);   // |tap|=5 -> cols 0-7 all zero
            #pragma unroll
            for (int kc = 0; kc < 2; kc++){
                uint32_t bh0[2], bh1[2], bl0[2], bl1[2];
                const int cb = ((m*2 + kc)*2 + 0)*2;
                const int cl = ((m*2 + kc)*2 + 1)*2;
                if (nf0live){
                    *(uint2*)bh0 = *(const uint2*)&bbuf[(cb+0)*64 + lane*2];
                    *(uint2*)bl0 = *(const uint2*)&bbuf[(cl+0)*64 + lane*2];
                }
                *(uint2*)bh1 = *(const uint2*)&bbuf[(cb+1)*64 + lane*2];
                *(uint2*)bl1 = *(const uint2*)&bbuf[(cl+1)*64 + lane*2];

                #pragma unroll
                for (int i = 0; i < 4; i++){
                    const uint32_t* pa = pHi + (rbase + i*16 + ro)*ROWF + kc*8 + tq;
                    const uint32_t* pl = pLo + (rbase + i*16 + ro)*ROWF + kc*8 + tq;
                    uint32_t ah[4] = { pa[0], pa[8*ROWF], pa[4], pa[8*ROWF + 4] };
                    uint32_t al[4] = { pl[0], pl[8*ROWF], pl[4], pl[8*ROWF + 4] };
                    if (nf0live){
                        mma8(acc[i][0], ah, bh0);
                        mma8(acc[i][0], al, bh0);
                        mma8(acc[i][0], ah, bl0);
                    }
                    mma8(acc[i][1], ah, bh1);
                    mma8(acc[i][1], al, bh1);
                    mma8(acc[i][1], ah, bl1);
                }
            }
        }

        // ---- Epilogue: ppv-count (v > -b) and max per filter column ----
        float negb[2][2], bb[2][2];
        #pragma unroll
        for (int nf = 0; nf < 2; nf++)
            #pragma unroll
            for (int j = 0; j < 2; j++){
                float b = bias_s[nf*8 + 2*tq + j];
                bb[nf][j] = b; negb[nf][j] = -b;
            }
        float cnt[2][2] = {{0.f,0.f},{0.f,0.f}};
        float mx [2][2] = {{NEGINF,NEGINF},{NEGINF,NEGINF}};
        #pragma unroll
        for (int i = 0; i < 4; i++)
            #pragma unroll
            for (int nf = 0; nf < 2; nf++){
                const float* A = acc[i][nf];
                cnt[nf][0] += (A[0] > negb[nf][0] ? 1.f : 0.f) + (A[2] > negb[nf][0] ? 1.f : 0.f);
                cnt[nf][1] += (A[1] > negb[nf][1] ? 1.f : 0.f) + (A[3] > negb[nf][1] ? 1.f : 0.f);
                mx[nf][0] = fmaxf(mx[nf][0], fmaxf(A[0], A[2]));
                mx[nf][1] = fmaxf(mx[nf][1], fmaxf(A[1], A[3]));
            }
        #pragma unroll
        for (int off = 4; off < 32; off <<= 1){
            #pragma unroll
            for (int nf = 0; nf < 2; nf++)
                #pragma unroll
                for (int j = 0; j < 2; j++){
                    cnt[nf][j] += __shfl_xor_sync(0xffffffffu, cnt[nf][j], off);
                    mx[nf][j]   = fmaxf(mx[nf][j], __shfl_xor_sync(0xffffffffu, mx[nf][j], off));
                }
        }
        if (lq == 0){
            #pragma unroll
            for (int nf = 0; nf < 2; nf++)
                #pragma unroll
                for (int j = 0; j < 2; j++){
                    int col = nf*8 + 2*tq + j;
                    red[(w*16 + col)*2 + 0] = cnt[nf][j];
                    red[(w*16 + col)*2 + 1] = mx[nf][j] + bb[nf][j];
                }
        }
        __syncthreads();
        if (t < 15){
            float cs = 0.0f, m2 = NEGINF;
            #pragma unroll
            for (int wi = 0; wi < NTH/32; wi++){
                cs += red[(wi*16 + t)*2 + 0];
                m2 = fmaxf(m2, red[(wi*16 + t)*2 + 1]);
            }
            int g = t / 5;
            int fid = g*30 + dlog*5 + (t - g*5);
            g_part[((size_t)n*NF + fid)*NTILES + tile] = make_float2(cs, m2);
        }
    }
}

// Combine tile partials, batch-normalize, write (512,180) output.
__global__ void rocket_finalize_kernel(float* __restrict__ out)
{
    __shared__ float sb[NTH];
    const int col = blockIdx.x;             // 0..179
    const int t   = threadIdx.x;
    const int kidx = col / 60;
    const int rem  = col - kidx * 60;
    const int j    = rem / 10;
    const int p    = (rem % 10) >> 1;
    const int s    = col & 1;               // 0 = ppv, 1 = max
    const int fid  = kidx * 30 + j * 5 + p;

    float raw[2];
    #pragma unroll
    for (int e = 0; e < 2; e++){
        int n = t + e * NTH;
        const float2* pp = &g_part[((size_t)n * NF + fid) * NTILES];
        float cs = 0.0f, m = NEGINF;
        #pragma unroll
        for (int tt = 0; tt < NTILES; tt++){
            float2 v = pp[tt];
            cs += v.x;
            m = fmaxf(m, v.y);
        }
        raw[e] = s ? m : cs * (1.0f / (float)LL);
    }

    // two-pass mean/var over the 512-sample batch
    sb[t] = raw[0] + raw[1];
    __syncthreads();
    for (int stp = NTH/2; stp > 0; stp >>= 1){
        if (t < stp) sb[t] += sb[t + stp];
        __syncthreads();
    }
    float mean = sb[0] * (1.0f / (float)NB);
    __syncthreads();
    float d0 = raw[0] - mean, d1 = raw[1] - mean;
    sb[t] = d0*d0 + d1*d1;
    __syncthreads();
    for (int stp = NTH/2; stp > 0; stp >>= 1){
        if (t < stp) sb[t] += sb[t + stp];
        __syncthreads();
    }
    float var = sb[0] * (1.0f / (float)NB);
    float inv = rsqrtf(var + 1e-5f);
    out[(size_t)t * 180 + col]         = d0 * inv;
    out[(size_t)(t + NTH) * 180 + col] = d1 * inv;
}

extern "C" void kernel_launch(void* const* d_in, const int* in_sizes, int n_in,
                              void* d_out, int out_size)
{
    const float* x   = (const float*)d_in[0];
    const float* W7  = (const float*)d_in[1];
    const float* b7  = (const float*)d_in[2];
    const float* W9  = (const float*)d_in[3];
    const float* b9  = (const float*)d_in[4];
    const float* W11 = (const float*)d_in[5];
    const float* b11 = (const float*)d_in[6];
    float* out = (float*)d_out;

    const int SMEM_BYTES = (2*WROWS*ROWF + 88*64) * 4 + (16 + 8*16*2) * 4 + 16;
    cudaFuncSetAttribute(rocket_mma_kernel,
                         cudaFuncAttributeMaxDynamicSharedMemorySize, SMEM_BYTES);

    dim3 grid(NTILES, NB);
    rocket_mma_kernel<<<grid, NTH, SMEM_BYTES>>>(x, W7, b7, W9, b9, W11, b11);
    rocket_finalize_kernel<<<180, NTH>>>(out);
}